// round 10
// baseline (speedup 1.0000x reference)
#include <cuda_runtime.h>
#include <math.h>

// Problem constants (SoftGatingMoE: B=4,S=2048,D=1024,E=8,H=1024,top_k=2)
#define BB 4
#define SS 2048
#define DD 1024
#define EE 8
#define HH 1024
#define TT (BB*SS)        // 8192 tokens
#define NSLOT (2*TT)      // 16384 (token, expert-slot) pairs
#define LBLK 32           // logits phase-A blocks (TT / 256)

// Packed fp32x2 helpers (Blackwell FFMA2 path — only reachable via PTX).
// Pack uses .b32 ("r") sources to match the proven mov.b64 pack idiom;
// fma.rn.f32x2 operates on .b64 ("l") registers.
#define FMA2(d, a, b) asm("fma.rn.f32x2 %0, %1, %2, %0;" : "+l"(d) : "l"(a), "l"(b))
#define PACK_DUP(d, f) do { unsigned int _u = __float_as_uint(f); \
    asm("mov.b64 %0, {%1, %1};" : "=l"(d) : "r"(_u)); } while (0)
#define UNPK(lo, hi, v) asm("mov.b64 {%0, %1}, %2;" : "=r"(lo), "=r"(hi) : "l"(v))

// -------- scratch (static device globals; no allocations) --------
__device__ int   g_counts[EE];
__device__ int   g_list[EE*TT];            // gslot ids grouped by expert
__device__ int   g_slot_expert[NSLOT];
__device__ float g_slot_w[NSLOT];
__device__ float g_hidden[(size_t)NSLOT*HH];   // 64 MB
__device__ float g_outslot[(size_t)NSLOT*DD];  // 64 MB (raw expert outputs)
__device__ float g_c[NSLOT];                   // dot(clf_w, outslot)
__device__ float g_partial[LBLK][32];          // per-block expert/batch bins
__device__ float g_pcnt[LBLK][BB];             // per-block nonpad counts

__global__ void zero_counts_kernel() {
    if (threadIdx.x < EE) g_counts[threadIdx.x] = 0;
}

// -------- gate: logits -> softmax -> routing output + top2 lists --------
__global__ __launch_bounds__(256) void gate_kernel(
    const float* __restrict__ x, const float* __restrict__ gw,
    float* __restrict__ rout)
{
    int t = blockIdx.x;
    __shared__ float sx[DD];
    __shared__ float sl[EE];
    __shared__ float sp[EE];
    int tid = threadIdx.x;
    const float4* xr = (const float4*)(x + (size_t)t * DD);
    ((float4*)sx)[tid] = xr[tid];           // 256 threads x float4 = 1024 floats
    __syncthreads();

    int w = tid >> 5, lane = tid & 31;
    if (w < EE) {
        float sum = 0.f;
        #pragma unroll 8
        for (int i = 0; i < DD/32; i++) {
            int d = lane + 32*i;
            sum += sx[d] * gw[d*EE + w];
        }
        #pragma unroll
        for (int o = 16; o; o >>= 1) sum += __shfl_xor_sync(0xffffffffu, sum, o);
        if (lane == 0) sl[w] = sum;
    }
    __syncthreads();

    if (tid == 0) {
        float m = sl[0];
        for (int e = 1; e < EE; e++) m = fmaxf(m, sl[e]);
        float s = 0.f;
        for (int e = 0; e < EE; e++) { float p = expf(sl[e] - m); sp[e] = p; s += p; }
        float inv = 1.f / s;
        for (int e = 0; e < EE; e++) sp[e] *= inv;
        // top-2, lowest index wins ties (matches jax.lax.top_k)
        int e0 = 0;
        for (int e = 1; e < EE; e++) if (sp[e] > sp[e0]) e0 = e;
        int e1 = (e0 == 0) ? 1 : 0;
        for (int e = 0; e < EE; e++) if (e != e0 && sp[e] > sp[e1]) e1 = e;
        float p0 = sp[e0], p1 = sp[e1];
        float r = 1.f / (p0 + p1);
        int gs0 = 2*t, gs1 = 2*t + 1;
        g_slot_expert[gs0] = e0; g_slot_w[gs0] = p0 * r;
        g_slot_expert[gs1] = e1; g_slot_w[gs1] = p1 * r;
        int pos0 = atomicAdd(&g_counts[e0], 1); g_list[e0*TT + pos0] = gs0;
        int pos1 = atomicAdd(&g_counts[e1], 1); g_list[e1*TT + pos1] = gs1;
    }
    __syncthreads();
    if (tid < EE) rout[(size_t)t*EE + tid] = sp[tid];
}

// -------- grouped GEMM 1: hidden = silu(x@w1_e) * (x@w3_e), gathered rows ----
// Tiles: 128(M) x 64(N) x 16(K), 256 threads.
// Microtile: 8 rows x 4 cols as 2 packed f32x2 col-pairs; dual B (w1,w3).
// A stored duplicated in smem (sAd[k][2m]=sAd[k][2m+1]=A[m][k]) so the inner
// loop loads (a,a) pairs directly. Software-pipelined via register prefetch.
// No forced minBlocks — reg pressure ~120-135; forcing 2 CTAs/SM would risk
// inner-loop spills (LDL/STL), which cost far more than occupancy buys.
__global__ __launch_bounds__(256) void ffn1_kernel(
    const float* __restrict__ x,
    const float* __restrict__ w1, const float* __restrict__ w3)
{
    int e = blockIdx.z;
    int cnt = g_counts[e];
    int mt = blockIdx.y;
    if (mt * 128 >= cnt) return;
    int n0 = blockIdx.x * 64;

    __shared__ float sAd[16][264];   // [k][2*m + dup], 256 used + pad
    __shared__ float sB1[16][64];
    __shared__ float sB3[16][64];

    int tid = threadIdx.x;
    int tx = tid & 15, ty = tid >> 4;        // cols tx*4 (2 pairs), rows ty*8..
    int arow = tid >> 1;                     // 0..127 (M row loaded)
    int apart = (tid & 1) * 8;               // k-offset 0 or 8
    int krow = tid >> 4, bseg = tid & 15;    // B: 16 k-rows x 16 float4 segs

    int am = mt * 128 + arow;
    int gsA = (am < cnt) ? g_list[e*TT + am] : -1;
    const float* arowp = (gsA >= 0) ? (x + (size_t)(gsA >> 1) * DD) : nullptr;
    const float* b1p = w1 + (size_t)e * DD * HH + (size_t)krow*HH + n0 + bseg*4;
    const float* b3p = w3 + (size_t)e * DD * HH + (size_t)krow*HH + n0 + bseg*4;

    unsigned long long acc1[16], acc3[16];   // [row*2 + pair]
    #pragma unroll
    for (int i = 0; i < 16; i++) { acc1[i] = 0ull; acc3[i] = 0ull; }

    // prologue: fetch tile 0
    float4 a0 = make_float4(0.f,0.f,0.f,0.f), a1 = a0;
    if (arowp) {
        a0 = *(const float4*)(arowp + apart);
        a1 = *(const float4*)(arowp + apart + 4);
    }
    float4 b1v = *(const float4*)(b1p);
    float4 b3v = *(const float4*)(b3p);

    for (int k0 = 0; k0 < DD; k0 += 16) {
        __syncthreads();
        {
            float av[8] = {a0.x,a0.y,a0.z,a0.w,a1.x,a1.y,a1.z,a1.w};
            #pragma unroll
            for (int i = 0; i < 8; i++) {
                unsigned long long dv;
                PACK_DUP(dv, av[i]);
                *(unsigned long long*)&sAd[apart + i][2*arow] = dv;
            }
            *(float4*)&sB1[krow][bseg*4] = b1v;
            *(float4*)&sB3[krow][bseg*4] = b3v;
        }
        __syncthreads();

        // issue next tile's loads (overlap with compute below)
        if (k0 + 16 < DD) {
            int kn = k0 + 16;
            if (arowp) {
                a0 = *(const float4*)(arowp + kn + apart);
                a1 = *(const float4*)(arowp + kn + apart + 4);
            }
            b1v = *(const float4*)(b1p + (size_t)kn*HH);
            b3v = *(const float4*)(b3p + (size_t)kn*HH);
        }

        #pragma unroll
        for (int kk = 0; kk < 16; kk++) {
            ulonglong2 b1 = *(const ulonglong2*)&sB1[kk][tx*4];
            ulonglong2 b3 = *(const ulonglong2*)&sB3[kk][tx*4];
            ulonglong2 p0 = *(const ulonglong2*)&sAd[kk][ty*16];
            ulonglong2 p1 = *(const ulonglong2*)&sAd[kk][ty*16 + 4];
            ulonglong2 p2 = *(const ulonglong2*)&sAd[kk][ty*16 + 8];
            ulonglong2 p3 = *(const ulonglong2*)&sAd[kk][ty*16 + 12];
            unsigned long long ar[8] = {p0.x, p0.y, p1.x, p1.y,
                                        p2.x, p2.y, p3.x, p3.y};
            #pragma unroll
            for (int i = 0; i < 8; i++) {
                FMA2(acc1[i*2 + 0], ar[i], b1.x);
                FMA2(acc1[i*2 + 1], ar[i], b1.y);
                FMA2(acc3[i*2 + 0], ar[i], b3.x);
                FMA2(acc3[i*2 + 1], ar[i], b3.y);
            }
        }
    }

    #pragma unroll
    for (int i = 0; i < 8; i++) {
        int gm = mt * 128 + ty*8 + i;
        if (gm >= cnt) continue;
        int gs = g_list[e*TT + gm];
        unsigned int u0, u1, u2, u3, v0, v1, v2, v3;
        UNPK(u0, u1, acc1[i*2 + 0]);
        UNPK(u2, u3, acc1[i*2 + 1]);
        UNPK(v0, v1, acc3[i*2 + 0]);
        UNPK(v2, v3, acc3[i*2 + 1]);
        float4 hv;
        float g;
        g = __uint_as_float(u0); hv.x = (g / (1.f + expf(-g))) * __uint_as_float(v0);
        g = __uint_as_float(u1); hv.y = (g / (1.f + expf(-g))) * __uint_as_float(v1);
        g = __uint_as_float(u2); hv.z = (g / (1.f + expf(-g))) * __uint_as_float(v2);
        g = __uint_as_float(u3); hv.w = (g / (1.f + expf(-g))) * __uint_as_float(v3);
        *(float4*)(g_hidden + (size_t)gs*HH + n0 + tx*4) = hv;
    }
}

// -------- grouped GEMM 2: outslot = hidden @ w2_e --------
// Tiles: 128(M) x 128(N) x 16(K), 256 threads.
// Microtile: 8 rows x 8 cols as 4 packed f32x2 col-pairs. Pipelined like ffn1.
__global__ __launch_bounds__(256) void ffn2_kernel(const float* __restrict__ w2)
{
    int e = blockIdx.z;
    int cnt = g_counts[e];
    int mt = blockIdx.y;
    if (mt * 128 >= cnt) return;
    int n0 = blockIdx.x * 128;

    __shared__ float sAd[16][264];
    __shared__ float sB[16][128];

    int tid = threadIdx.x;
    int tx = tid & 15, ty = tid >> 4;        // cols tx*8 (4 pairs), rows ty*8..
    int arow = tid >> 1;
    int apart = (tid & 1) * 8;
    int krow = tid >> 4, bseg = tid & 15;    // B: 16 k-rows x 16 segs of 8 floats

    int am = mt * 128 + arow;
    int gsA = (am < cnt) ? g_list[e*TT + am] : -1;
    const float* arowp = (gsA >= 0) ? (g_hidden + (size_t)gsA * HH) : nullptr;
    const float* bp = w2 + (size_t)e * HH * DD + (size_t)krow*DD + n0 + bseg*8;

    unsigned long long acc[32];              // [row*4 + pair]
    #pragma unroll
    for (int i = 0; i < 32; i++) acc[i] = 0ull;

    // prologue: fetch tile 0
    float4 a0 = make_float4(0.f,0.f,0.f,0.f), a1 = a0;
    if (arowp) {
        a0 = *(const float4*)(arowp + apart);
        a1 = *(const float4*)(arowp + apart + 4);
    }
    float4 bv0 = *(const float4*)(bp);
    float4 bv1 = *(const float4*)(bp + 4);

    for (int k0 = 0; k0 < HH; k0 += 16) {
        __syncthreads();
        {
            float av[8] = {a0.x,a0.y,a0.z,a0.w,a1.x,a1.y,a1.z,a1.w};
            #pragma unroll
            for (int i = 0; i < 8; i++) {
                unsigned long long dv;
                PACK_DUP(dv, av[i]);
                *(unsigned long long*)&sAd[apart + i][2*arow] = dv;
            }
            *(float4*)&sB[krow][bseg*8]     = bv0;
            *(float4*)&sB[krow][bseg*8 + 4] = bv1;
        }
        __syncthreads();

        if (k0 + 16 < HH) {
            int kn = k0 + 16;
            if (arowp) {
                a0 = *(const float4*)(arowp + kn + apart);
                a1 = *(const float4*)(arowp + kn + apart + 4);
            }
            bv0 = *(const float4*)(bp + (size_t)kn*DD);
            bv1 = *(const float4*)(bp + (size_t)kn*DD + 4);
        }

        #pragma unroll
        for (int kk = 0; kk < 16; kk++) {
            ulonglong2 bq0 = *(const ulonglong2*)&sB[kk][tx*8];
            ulonglong2 bq1 = *(const ulonglong2*)&sB[kk][tx*8 + 4];
            unsigned long long bb[4] = {bq0.x, bq0.y, bq1.x, bq1.y};
            ulonglong2 p0 = *(const ulonglong2*)&sAd[kk][ty*16];
            ulonglong2 p1 = *(const ulonglong2*)&sAd[kk][ty*16 + 4];
            ulonglong2 p2 = *(const ulonglong2*)&sAd[kk][ty*16 + 8];
            ulonglong2 p3 = *(const ulonglong2*)&sAd[kk][ty*16 + 12];
            unsigned long long ar[8] = {p0.x, p0.y, p1.x, p1.y,
                                        p2.x, p2.y, p3.x, p3.y};
            #pragma unroll
            for (int i = 0; i < 8; i++) {
                #pragma unroll
                for (int j = 0; j < 4; j++) FMA2(acc[i*4 + j], ar[i], bb[j]);
            }
        }
    }

    #pragma unroll
    for (int i = 0; i < 8; i++) {
        int gm = mt * 128 + ty*8 + i;
        if (gm >= cnt) continue;
        int gs = g_list[e*TT + gm];
        float* op = g_outslot + (size_t)gs*DD + n0 + tx*8;
        unsigned int c0, c1, c2, c3, c4, c5, c6, c7;
        UNPK(c0, c1, acc[i*4 + 0]);
        UNPK(c2, c3, acc[i*4 + 1]);
        UNPK(c4, c5, acc[i*4 + 2]);
        UNPK(c6, c7, acc[i*4 + 3]);
        float4 o0 = make_float4(__uint_as_float(c0), __uint_as_float(c1),
                                __uint_as_float(c2), __uint_as_float(c3));
        float4 o1 = make_float4(__uint_as_float(c4), __uint_as_float(c5),
                                __uint_as_float(c6), __uint_as_float(c7));
        *(float4*)(op)     = o0;
        *(float4*)(op + 4) = o1;
    }
}

// -------- fused combine + classifier-dot: one pass over g_outslot -----------
// final[t] = w0*out[2t] + w1*out[2t+1];  g_c[gs] = dot(clf_w, out[gs]).
// Reductions are fixed-order (warp shuffle + smem tree) -> deterministic.
__global__ __launch_bounds__(256) void combine_clf_kernel(
    const float* __restrict__ clf_w, float* __restrict__ outp)
{
    int t = blockIdx.x;
    int tid = threadIdx.x;
    float w0 = g_slot_w[2*t], w1 = g_slot_w[2*t + 1];
    const float4* o0 = (const float4*)(g_outslot + (size_t)(2*t) * DD);
    const float4* o1 = (const float4*)(g_outslot + (size_t)(2*t + 1) * DD);
    const float4* cw = (const float4*)clf_w;

    float4 a = o0[tid], b = o1[tid], c = cw[tid], r;
    r.x = w0*a.x + w1*b.x;
    r.y = w0*a.y + w1*b.y;
    r.z = w0*a.z + w1*b.z;
    r.w = w0*a.w + w1*b.w;
    ((float4*)(outp + (size_t)t * DD))[tid] = r;

    float d0 = c.x*a.x + c.y*a.y + c.z*a.z + c.w*a.w;
    float d1 = c.x*b.x + c.y*b.y + c.z*b.z + c.w*b.w;
    #pragma unroll
    for (int o = 16; o; o >>= 1) {
        d0 += __shfl_xor_sync(0xffffffffu, d0, o);
        d1 += __shfl_xor_sync(0xffffffffu, d1, o);
    }
    __shared__ float s0[8], s1[8];
    int w = tid >> 5, lane = tid & 31;
    if (lane == 0) { s0[w] = d0; s1[w] = d1; }
    __syncthreads();
    if (tid == 0) {
        float t0 = 0.f, t1 = 0.f;
        #pragma unroll
        for (int i = 0; i < 8; i++) { t0 += s0[i]; t1 += s1[i]; }
        g_c[2*t]     = t0;
        g_c[2*t + 1] = t1;
    }
}

// -------- expert logits, phase A: per-block partial bins (deterministic) ----
// 32 blocks x 256 threads, one token per thread; fixed-order smem tree.
// pads read as 32-bit words; nonzero == True (valid for int32 or f32 bools)
__global__ __launch_bounds__(256) void logits_partial_kernel(
    const int* __restrict__ pad1, const int* __restrict__ pad2)
{
    __shared__ float sbin[256][33];   // 32 bins (e*B+b), padded
    __shared__ float scnt[256][5];    // nonpad counts per batch
    int tid = threadIdx.x;
    int bk = blockIdx.x;
    #pragma unroll
    for (int k = 0; k < 32; k++) sbin[tid][k] = 0.f;
    #pragma unroll
    for (int b = 0; b < BB; b++) scnt[tid][b] = 0.f;

    int t = bk * 256 + tid;
    bool np = (pad1[t] == 0) && (pad2[t] == 0);
    if (np) {
        int b = t / SS;
        scnt[tid][b] = 1.f;
        int gs0 = 2*t, gs1 = 2*t + 1;
        sbin[tid][g_slot_expert[gs0]*BB + b] += g_slot_w[gs0] * g_c[gs0];
        sbin[tid][g_slot_expert[gs1]*BB + b] += g_slot_w[gs1] * g_c[gs1];
    }
    __syncthreads();
    for (int st = 128; st > 0; st >>= 1) {
        if (tid < st) {
            #pragma unroll
            for (int k = 0; k < 32; k++) sbin[tid][k] += sbin[tid + st][k];
            #pragma unroll
            for (int b = 0; b < BB; b++) scnt[tid][b] += scnt[tid + st][b];
        }
        __syncthreads();
    }
    if (tid < 32) g_partial[bk][tid] = sbin[0][tid];
    if (tid < BB) g_pcnt[bk][tid] = scnt[0][tid];
}

// -------- expert logits, phase B: reduce 32 partials, cumsum, emit ----------
__global__ __launch_bounds__(32) void logits_reduce_kernel(
    const float* __restrict__ clf_b, float* __restrict__ outLog)
{
    __shared__ float bins[32];
    __shared__ float cnts[BB];
    int tid = threadIdx.x;
    float s = 0.f;
    for (int bk = 0; bk < LBLK; bk++) s += g_partial[bk][tid];  // fixed order
    bins[tid] = s;
    if (tid < BB) {
        float c = 0.f;
        for (int bk = 0; bk < LBLK; bk++) c += g_pcnt[bk][tid];
        cnts[tid] = c;
    }
    __syncwarp();
    if (tid == 0) {
        float cb = clf_b[0];
        for (int b = 0; b < BB; b++) {
            float run = 0.f;
            float invc = 1.f / cnts[b];
            for (int e = 0; e < EE; e++) {
                run += bins[e*BB + b] * invc;
                outLog[e*BB + b] = run + cb;   // [E,B,1] flattened
            }
        }
    }
}

// -------- launch --------
// Inputs (metadata order): x, tgt_pad, tgt_mask_id_bool, top_k, gate_w,
//                          w1, w2, w3, clf_w, clf_b
// Output: [final (T*D) | expert_logits (E*B) | routing_weights (T*E)] fp32
extern "C" void kernel_launch(void* const* d_in, const int* in_sizes, int n_in,
                              void* d_out, int out_size)
{
    const float* x    = (const float*)d_in[0];
    const int*   pad1 = (const int*)d_in[1];
    const int*   pad2 = (const int*)d_in[2];
    const float* gw   = (const float*)d_in[4];
    const float* w1   = (const float*)d_in[5];
    const float* w2   = (const float*)d_in[6];
    const float* w3   = (const float*)d_in[7];
    const float* clfw = (const float*)d_in[8];
    const float* clfb = (const float*)d_in[9];

    float* out       = (float*)d_out;
    float* out_final = out;
    float* out_log   = out + (size_t)TT * DD;
    float* out_rout  = out + (size_t)TT * DD + (size_t)EE * BB;

    zero_counts_kernel<<<1, 32>>>();
    gate_kernel<<<TT, 256>>>(x, gw, out_rout);

    dim3 g1(HH/64, TT/128, EE);
    ffn1_kernel<<<g1, 256>>>(x, w1, w3);

    dim3 g2(DD/128, TT/128, EE);
    ffn2_kernel<<<g2, 256>>>(w2);

    combine_clf_kernel<<<TT, 256>>>(clfw, out_final);
    logits_partial_kernel<<<LBLK, 256>>>(pad1, pad2);
    logits_reduce_kernel<<<1, 32>>>(clfb, out_log);
}

// round 15
// speedup vs baseline: 1.1664x; 1.1664x over previous
#include <cuda_runtime.h>
#include <math.h>

// Problem constants (SoftGatingMoE: B=4,S=2048,D=1024,E=8,H=1024,top_k=2)
#define BB 4
#define SS 2048
#define DD 1024
#define EE 8
#define HH 1024
#define TT (BB*SS)        // 8192 tokens
#define NSLOT (2*TT)      // 16384 (token, expert-slot) pairs
#define LBLK 32           // logits phase-A blocks (TT / 256)

// Packed fp32x2 helpers (Blackwell FFMA2 path — only reachable via PTX).
#define FMA2(d, a, b) asm("fma.rn.f32x2 %0, %1, %2, %0;" : "+l"(d) : "l"(a), "l"(b))
#define PACK_DUP(d, f) do { unsigned int _u = __float_as_uint(f); \
    asm("mov.b64 %0, {%1, %1};" : "=l"(d) : "r"(_u)); } while (0)
#define UNPK(lo, hi, v) asm("mov.b64 {%0, %1}, %2;" : "=r"(lo), "=r"(hi) : "l"(v))

// -------- scratch (static device globals; no allocations) --------
__device__ int   g_counts[EE];
__device__ int   g_list[EE*TT];            // gslot ids grouped by expert
__device__ int   g_slot_expert[NSLOT];
__device__ float g_slot_w[NSLOT];
__device__ float g_hidden[(size_t)NSLOT*HH];   // 64 MB
__device__ float g_outslot[(size_t)NSLOT*DD];  // 64 MB (raw expert outputs)
__device__ float g_c[NSLOT];                   // dot(clf_w, outslot)
__device__ float g_partial[LBLK][32];          // per-block expert/batch bins
__device__ float g_pcnt[LBLK][BB];             // per-block nonpad counts

__global__ void zero_counts_kernel() {
    if (threadIdx.x < EE) g_counts[threadIdx.x] = 0;
}

// -------- gate: logits -> softmax -> routing output + top2 lists --------
__global__ __launch_bounds__(256) void gate_kernel(
    const float* __restrict__ x, const float* __restrict__ gw,
    float* __restrict__ rout)
{
    int t = blockIdx.x;
    __shared__ float sx[DD];
    __shared__ float sl[EE];
    __shared__ float sp[EE];
    int tid = threadIdx.x;
    const float4* xr = (const float4*)(x + (size_t)t * DD);
    ((float4*)sx)[tid] = xr[tid];           // 256 threads x float4 = 1024 floats
    __syncthreads();

    int w = tid >> 5, lane = tid & 31;
    if (w < EE) {
        float sum = 0.f;
        #pragma unroll 8
        for (int i = 0; i < DD/32; i++) {
            int d = lane + 32*i;
            sum += sx[d] * gw[d*EE + w];
        }
        #pragma unroll
        for (int o = 16; o; o >>= 1) sum += __shfl_xor_sync(0xffffffffu, sum, o);
        if (lane == 0) sl[w] = sum;
    }
    __syncthreads();

    if (tid == 0) {
        float m = sl[0];
        for (int e = 1; e < EE; e++) m = fmaxf(m, sl[e]);
        float s = 0.f;
        for (int e = 0; e < EE; e++) { float p = expf(sl[e] - m); sp[e] = p; s += p; }
        float inv = 1.f / s;
        for (int e = 0; e < EE; e++) sp[e] *= inv;
        // top-2, lowest index wins ties (matches jax.lax.top_k)
        int e0 = 0;
        for (int e = 1; e < EE; e++) if (sp[e] > sp[e0]) e0 = e;
        int e1 = (e0 == 0) ? 1 : 0;
        for (int e = 0; e < EE; e++) if (e != e0 && sp[e] > sp[e1]) e1 = e;
        float p0 = sp[e0], p1 = sp[e1];
        float r = 1.f / (p0 + p1);
        int gs0 = 2*t, gs1 = 2*t + 1;
        g_slot_expert[gs0] = e0; g_slot_w[gs0] = p0 * r;
        g_slot_expert[gs1] = e1; g_slot_w[gs1] = p1 * r;
        int pos0 = atomicAdd(&g_counts[e0], 1); g_list[e0*TT + pos0] = gs0;
        int pos1 = atomicAdd(&g_counts[e1], 1); g_list[e1*TT + pos1] = gs1;
    }
    __syncthreads();
    if (tid < EE) rout[(size_t)t*EE + tid] = sp[tid];
}

// -------- grouped GEMM 1: hidden = silu(x@w1_e) * (x@w3_e), gathered rows ----
// Tiles: 128(M) x 64(N) x 16(K), 256 threads.
// Microtile: 8 rows x 4 cols as 2 packed f32x2 col-pairs; dual B (w1,w3).
// A stored NON-duplicated in smem ([k][m]); the (a,a) packed pairs are built
// in registers (ALU MOVs) — halves A LDS traffic vs the dup-in-smem layout,
// which ncu showed saturating L1TEX (94%) while FMA idled at 50%.
__global__ __launch_bounds__(256) void ffn1_kernel(
    const float* __restrict__ x,
    const float* __restrict__ w1, const float* __restrict__ w3)
{
    int e = blockIdx.z;
    int cnt = g_counts[e];
    int mt = blockIdx.y;
    if (mt * 128 >= cnt) return;
    int n0 = blockIdx.x * 64;

    __shared__ float sA[16][136];    // [k][m], 128 used + pad (16B-aligned rows)
    __shared__ float sB1[16][64];
    __shared__ float sB3[16][64];

    int tid = threadIdx.x;
    int tx = tid & 15, ty = tid >> 4;        // cols tx*4 (2 pairs), rows ty*8..
    int arow = tid >> 1;                     // 0..127 (M row loaded)
    int apart = (tid & 1) * 8;               // k-offset 0 or 8
    int krow = tid >> 4, bseg = tid & 15;    // B: 16 k-rows x 16 float4 segs

    int am = mt * 128 + arow;
    int gsA = (am < cnt) ? g_list[e*TT + am] : -1;
    const float* arowp = (gsA >= 0) ? (x + (size_t)(gsA >> 1) * DD) : nullptr;
    const float* b1p = w1 + (size_t)e * DD * HH + (size_t)krow*HH + n0 + bseg*4;
    const float* b3p = w3 + (size_t)e * DD * HH + (size_t)krow*HH + n0 + bseg*4;

    unsigned long long acc1[16], acc3[16];   // [row*2 + pair]
    #pragma unroll
    for (int i = 0; i < 16; i++) { acc1[i] = 0ull; acc3[i] = 0ull; }

    // prologue: fetch tile 0
    float4 a0 = make_float4(0.f,0.f,0.f,0.f), a1 = a0;
    if (arowp) {
        a0 = *(const float4*)(arowp + apart);
        a1 = *(const float4*)(arowp + apart + 4);
    }
    float4 b1v = *(const float4*)(b1p);
    float4 b3v = *(const float4*)(b3p);

    for (int k0 = 0; k0 < DD; k0 += 16) {
        __syncthreads();
        {
            sA[apart + 0][arow] = a0.x;
            sA[apart + 1][arow] = a0.y;
            sA[apart + 2][arow] = a0.z;
            sA[apart + 3][arow] = a0.w;
            sA[apart + 4][arow] = a1.x;
            sA[apart + 5][arow] = a1.y;
            sA[apart + 6][arow] = a1.z;
            sA[apart + 7][arow] = a1.w;
            *(float4*)&sB1[krow][bseg*4] = b1v;
            *(float4*)&sB3[krow][bseg*4] = b3v;
        }
        __syncthreads();

        // issue next tile's loads (overlap with compute below)
        if (k0 + 16 < DD) {
            int kn = k0 + 16;
            if (arowp) {
                a0 = *(const float4*)(arowp + kn + apart);
                a1 = *(const float4*)(arowp + kn + apart + 4);
            }
            b1v = *(const float4*)(b1p + (size_t)kn*HH);
            b3v = *(const float4*)(b3p + (size_t)kn*HH);
        }

        #pragma unroll
        for (int kk = 0; kk < 16; kk++) {
            ulonglong2 b1 = *(const ulonglong2*)&sB1[kk][tx*4];
            ulonglong2 b3 = *(const ulonglong2*)&sB3[kk][tx*4];
            float4 am0 = *(const float4*)&sA[kk][ty*8];
            float4 am1 = *(const float4*)&sA[kk][ty*8 + 4];
            unsigned long long ar[8];
            PACK_DUP(ar[0], am0.x); PACK_DUP(ar[1], am0.y);
            PACK_DUP(ar[2], am0.z); PACK_DUP(ar[3], am0.w);
            PACK_DUP(ar[4], am1.x); PACK_DUP(ar[5], am1.y);
            PACK_DUP(ar[6], am1.z); PACK_DUP(ar[7], am1.w);
            #pragma unroll
            for (int i = 0; i < 8; i++) {
                FMA2(acc1[i*2 + 0], ar[i], b1.x);
                FMA2(acc1[i*2 + 1], ar[i], b1.y);
                FMA2(acc3[i*2 + 0], ar[i], b3.x);
                FMA2(acc3[i*2 + 1], ar[i], b3.y);
            }
        }
    }

    #pragma unroll
    for (int i = 0; i < 8; i++) {
        int gm = mt * 128 + ty*8 + i;
        if (gm >= cnt) continue;
        int gs = g_list[e*TT + gm];
        unsigned int u0, u1, u2, u3, v0, v1, v2, v3;
        UNPK(u0, u1, acc1[i*2 + 0]);
        UNPK(u2, u3, acc1[i*2 + 1]);
        UNPK(v0, v1, acc3[i*2 + 0]);
        UNPK(v2, v3, acc3[i*2 + 1]);
        float4 hv;
        float g;
        g = __uint_as_float(u0); hv.x = (g / (1.f + expf(-g))) * __uint_as_float(v0);
        g = __uint_as_float(u1); hv.y = (g / (1.f + expf(-g))) * __uint_as_float(v1);
        g = __uint_as_float(u2); hv.z = (g / (1.f + expf(-g))) * __uint_as_float(v2);
        g = __uint_as_float(u3); hv.w = (g / (1.f + expf(-g))) * __uint_as_float(v3);
        *(float4*)(g_hidden + (size_t)gs*HH + n0 + tx*4) = hv;
    }
}

// -------- grouped GEMM 2: outslot = hidden @ w2_e --------
// Tiles: 128(M) x 128(N) x 16(K), 256 threads.
// Microtile: 8 rows x 8 cols as 4 packed f32x2 col-pairs. A non-dup like ffn1.
__global__ __launch_bounds__(256) void ffn2_kernel(const float* __restrict__ w2)
{
    int e = blockIdx.z;
    int cnt = g_counts[e];
    int mt = blockIdx.y;
    if (mt * 128 >= cnt) return;
    int n0 = blockIdx.x * 128;

    __shared__ float sA[16][136];
    __shared__ float sB[16][128];

    int tid = threadIdx.x;
    int tx = tid & 15, ty = tid >> 4;        // cols tx*8 (4 pairs), rows ty*8..
    int arow = tid >> 1;
    int apart = (tid & 1) * 8;
    int krow = tid >> 4, bseg = tid & 15;    // B: 16 k-rows x 16 segs of 8 floats

    int am = mt * 128 + arow;
    int gsA = (am < cnt) ? g_list[e*TT + am] : -1;
    const float* arowp = (gsA >= 0) ? (g_hidden + (size_t)gsA * HH) : nullptr;
    const float* bp = w2 + (size_t)e * HH * DD + (size_t)krow*DD + n0 + bseg*8;

    unsigned long long acc[32];              // [row*4 + pair]
    #pragma unroll
    for (int i = 0; i < 32; i++) acc[i] = 0ull;

    // prologue: fetch tile 0
    float4 a0 = make_float4(0.f,0.f,0.f,0.f), a1 = a0;
    if (arowp) {
        a0 = *(const float4*)(arowp + apart);
        a1 = *(const float4*)(arowp + apart + 4);
    }
    float4 bv0 = *(const float4*)(bp);
    float4 bv1 = *(const float4*)(bp + 4);

    for (int k0 = 0; k0 < HH; k0 += 16) {
        __syncthreads();
        {
            sA[apart + 0][arow] = a0.x;
            sA[apart + 1][arow] = a0.y;
            sA[apart + 2][arow] = a0.z;
            sA[apart + 3][arow] = a0.w;
            sA[apart + 4][arow] = a1.x;
            sA[apart + 5][arow] = a1.y;
            sA[apart + 6][arow] = a1.z;
            sA[apart + 7][arow] = a1.w;
            *(float4*)&sB[krow][bseg*8]     = bv0;
            *(float4*)&sB[krow][bseg*8 + 4] = bv1;
        }
        __syncthreads();

        if (k0 + 16 < HH) {
            int kn = k0 + 16;
            if (arowp) {
                a0 = *(const float4*)(arowp + kn + apart);
                a1 = *(const float4*)(arowp + kn + apart + 4);
            }
            bv0 = *(const float4*)(bp + (size_t)kn*DD);
            bv1 = *(const float4*)(bp + (size_t)kn*DD + 4);
        }

        #pragma unroll
        for (int kk = 0; kk < 16; kk++) {
            ulonglong2 bq0 = *(const ulonglong2*)&sB[kk][tx*8];
            ulonglong2 bq1 = *(const ulonglong2*)&sB[kk][tx*8 + 4];
            unsigned long long bb[4] = {bq0.x, bq0.y, bq1.x, bq1.y};
            float4 am0 = *(const float4*)&sA[kk][ty*8];
            float4 am1 = *(const float4*)&sA[kk][ty*8 + 4];
            unsigned long long ar[8];
            PACK_DUP(ar[0], am0.x); PACK_DUP(ar[1], am0.y);
            PACK_DUP(ar[2], am0.z); PACK_DUP(ar[3], am0.w);
            PACK_DUP(ar[4], am1.x); PACK_DUP(ar[5], am1.y);
            PACK_DUP(ar[6], am1.z); PACK_DUP(ar[7], am1.w);
            #pragma unroll
            for (int i = 0; i < 8; i++) {
                #pragma unroll
                for (int j = 0; j < 4; j++) FMA2(acc[i*4 + j], ar[i], bb[j]);
            }
        }
    }

    #pragma unroll
    for (int i = 0; i < 8; i++) {
        int gm = mt * 128 + ty*8 + i;
        if (gm >= cnt) continue;
        int gs = g_list[e*TT + gm];
        float* op = g_outslot + (size_t)gs*DD + n0 + tx*8;
        unsigned int c0, c1, c2, c3, c4, c5, c6, c7;
        UNPK(c0, c1, acc[i*4 + 0]);
        UNPK(c2, c3, acc[i*4 + 1]);
        UNPK(c4, c5, acc[i*4 + 2]);
        UNPK(c6, c7, acc[i*4 + 3]);
        float4 o0 = make_float4(__uint_as_float(c0), __uint_as_float(c1),
                                __uint_as_float(c2), __uint_as_float(c3));
        float4 o1 = make_float4(__uint_as_float(c4), __uint_as_float(c5),
                                __uint_as_float(c6), __uint_as_float(c7));
        *(float4*)(op)     = o0;
        *(float4*)(op + 4) = o1;
    }
}

// -------- fused combine + classifier-dot: one pass over g_outslot -----------
__global__ __launch_bounds__(256) void combine_clf_kernel(
    const float* __restrict__ clf_w, float* __restrict__ outp)
{
    int t = blockIdx.x;
    int tid = threadIdx.x;
    float w0 = g_slot_w[2*t], w1 = g_slot_w[2*t + 1];
    const float4* o0 = (const float4*)(g_outslot + (size_t)(2*t) * DD);
    const float4* o1 = (const float4*)(g_outslot + (size_t)(2*t + 1) * DD);
    const float4* cw = (const float4*)clf_w;

    float4 a = o0[tid], b = o1[tid], c = cw[tid], r;
    r.x = w0*a.x + w1*b.x;
    r.y = w0*a.y + w1*b.y;
    r.z = w0*a.z + w1*b.z;
    r.w = w0*a.w + w1*b.w;
    ((float4*)(outp + (size_t)t * DD))[tid] = r;

    float d0 = c.x*a.x + c.y*a.y + c.z*a.z + c.w*a.w;
    float d1 = c.x*b.x + c.y*b.y + c.z*b.z + c.w*b.w;
    #pragma unroll
    for (int o = 16; o; o >>= 1) {
        d0 += __shfl_xor_sync(0xffffffffu, d0, o);
        d1 += __shfl_xor_sync(0xffffffffu, d1, o);
    }
    __shared__ float s0[8], s1[8];
    int w = tid >> 5, lane = tid & 31;
    if (lane == 0) { s0[w] = d0; s1[w] = d1; }
    __syncthreads();
    if (tid == 0) {
        float t0 = 0.f, t1 = 0.f;
        #pragma unroll
        for (int i = 0; i < 8; i++) { t0 += s0[i]; t1 += s1[i]; }
        g_c[2*t]     = t0;
        g_c[2*t + 1] = t1;
    }
}

// -------- expert logits, phase A: per-block partial bins (deterministic) ----
__global__ __launch_bounds__(256) void logits_partial_kernel(
    const int* __restrict__ pad1, const int* __restrict__ pad2)
{
    __shared__ float sbin[256][33];   // 32 bins (e*B+b), padded
    __shared__ float scnt[256][5];    // nonpad counts per batch
    int tid = threadIdx.x;
    int bk = blockIdx.x;
    #pragma unroll
    for (int k = 0; k < 32; k++) sbin[tid][k] = 0.f;
    #pragma unroll
    for (int b = 0; b < BB; b++) scnt[tid][b] = 0.f;

    int t = bk * 256 + tid;
    bool np = (pad1[t] == 0) && (pad2[t] == 0);
    if (np) {
        int b = t / SS;
        scnt[tid][b] = 1.f;
        int gs0 = 2*t, gs1 = 2*t + 1;
        sbin[tid][g_slot_expert[gs0]*BB + b] += g_slot_w[gs0] * g_c[gs0];
        sbin[tid][g_slot_expert[gs1]*BB + b] += g_slot_w[gs1] * g_c[gs1];
    }
    __syncthreads();
    for (int st = 128; st > 0; st >>= 1) {
        if (tid < st) {
            #pragma unroll
            for (int k = 0; k < 32; k++) sbin[tid][k] += sbin[tid + st][k];
            #pragma unroll
            for (int b = 0; b < BB; b++) scnt[tid][b] += scnt[tid + st][b];
        }
        __syncthreads();
    }
    if (tid < 32) g_partial[bk][tid] = sbin[0][tid];
    if (tid < BB) g_pcnt[bk][tid] = scnt[0][tid];
}

// -------- expert logits, phase B: reduce 32 partials, cumsum, emit ----------
__global__ __launch_bounds__(32) void logits_reduce_kernel(
    const float* __restrict__ clf_b, float* __restrict__ outLog)
{
    __shared__ float bins[32];
    __shared__ float cnts[BB];
    int tid = threadIdx.x;
    float s = 0.f;
    for (int bk = 0; bk < LBLK; bk++) s += g_partial[bk][tid];  // fixed order
    bins[tid] = s;
    if (tid < BB) {
        float c = 0.f;
        for (int bk = 0; bk < LBLK; bk++) c += g_pcnt[bk][tid];
        cnts[tid] = c;
    }
    __syncwarp();
    if (tid == 0) {
        float cb = clf_b[0];
        for (int b = 0; b < BB; b++) {
            float run = 0.f;
            float invc = 1.f / cnts[b];
            for (int e = 0; e < EE; e++) {
                run += bins[e*BB + b] * invc;
                outLog[e*BB + b] = run + cb;   // [E,B,1] flattened
            }
        }
    }
}

// -------- launch --------
// Inputs (metadata order): x, tgt_pad, tgt_mask_id_bool, top_k, gate_w,
//                          w1, w2, w3, clf_w, clf_b
// Output: [final (T*D) | expert_logits (E*B) | routing_weights (T*E)] fp32
extern "C" void kernel_launch(void* const* d_in, const int* in_sizes, int n_in,
                              void* d_out, int out_size)
{
    const float* x    = (const float*)d_in[0];
    const int*   pad1 = (const int*)d_in[1];
    const int*   pad2 = (const int*)d_in[2];
    const float* gw   = (const float*)d_in[4];
    const float* w1   = (const float*)d_in[5];
    const float* w2   = (const float*)d_in[6];
    const float* w3   = (const float*)d_in[7];
    const float* clfw = (const float*)d_in[8];
    const float* clfb = (const float*)d_in[9];

    float* out       = (float*)d_out;
    float* out_final = out;
    float* out_log   = out + (size_t)TT * DD;
    float* out_rout  = out + (size_t)TT * DD + (size_t)EE * BB;

    zero_counts_kernel<<<1, 32>>>();
    gate_kernel<<<TT, 256>>>(x, gw, out_rout);

    dim3 g1(HH/64, TT/128, EE);
    ffn1_kernel<<<g1, 256>>>(x, w1, w3);

    dim3 g2(DD/128, TT/128, EE);
    ffn2_kernel<<<g2, 256>>>(w2);

    combine_clf_kernel<<<TT, 256>>>(clfw, out_final);
    logits_partial_kernel<<<LBLK, 256>>>(pad1, pad2);
    logits_reduce_kernel<<<1, 32>>>(clfb, out_log);
}